// round 15
// baseline (speedup 1.0000x reference)
#include <cuda_runtime.h>
#include <cuda_bf16.h>
#include <cstdint>

#define NN 100000
#define NE 1600000
#define DD 128

// ---------------- scratch (device globals; referenced ONLY in device code) --
__device__ int   g_off[NN + 1];
__device__ int   g_cnt[NN];         // histogram; k_scan zeroes it for replays
__device__ float g_inv[NN];
__device__ int   g_btot[128];
__device__ int   g_bbase[128];
__device__ int   g_done;            // scan last-block counter (self-resetting)
__device__ __align__(16) int g_srcs[NE];
__device__ __align__(16) int g_dr[2 * NE];   // (dst, rank) pairs
__device__ __align__(16) float g_h[NN * DD]; // fp32 hidden acts (for agg2 gather)
__device__ __align__(16) unsigned short g_xhi[NN * DD], g_xlo[NN * DD];
__device__ __align__(16) unsigned short g_mhi[NN * DD], g_mlo[NN * DD];
__device__ __align__(16) unsigned short g_hhi[NN * DD], g_hlo[NN * DD];
__device__ __align__(16) unsigned short g_w1lhi[DD*DD], g_w1llo[DD*DD];
__device__ __align__(16) unsigned short g_w1rhi[DD*DD], g_w1rlo[DD*DD];
__device__ __align__(16) unsigned short g_w2lhi[DD*DD], g_w2llo[DD*DD];
__device__ __align__(16) unsigned short g_w2rhi[DD*DD], g_w2rlo[DD*DD];

__device__ __forceinline__ void split1(float v, unsigned short& hi, unsigned short& lo) {
    __nv_bfloat16 h = __float2bfloat16(v);
    __nv_bfloat16 l = __float2bfloat16(v - __bfloat162float(h));
    hi = *(unsigned short*)&h; lo = *(unsigned short*)&l;
}

// ---------------- build 1: dst convert + histogram + rank (2 edges/thread) --
__global__ void k_hist(const void* __restrict__ ei) {
    const int* w = (const int*)ei;
    bool is32 = (w[1] | w[3] | w[5] | w[7] | w[9] | w[11] | w[13] | w[15]) != 0;
    int i = (blockIdx.x * blockDim.x + threadIdx.x) * 2;
    if (i >= NE) return;
    int d0, d1;
    if (is32) {
        int2 dd = *(const int2*)((const int*)ei + NE + i);
        d0 = dd.x; d1 = dd.y;
    } else {
        longlong2 dd = *(const longlong2*)((const long long*)ei + NE + i);
        d0 = (int)dd.x; d1 = (int)dd.y;
    }
    int r0 = 0, r1 = 0;
    if (d0 >= 0 && d0 < NN) r0 = atomicAdd(&g_cnt[d0], 1);
    if (d1 >= 0 && d1 < NN) r1 = atomicAdd(&g_cnt[d1], 1);
    *(int4*)(g_dr + 2 * i) = make_int4(d0, r0, d1, r1);
}

// ---------------- build 2: scan (fused level-2, zeroes g_cnt for replays) ---
__device__ __forceinline__ int wscan(int x, int lane) {
    #pragma unroll
    for (int o = 1; o < 32; o <<= 1) {
        int t = __shfl_up_sync(0xffffffffu, x, o);
        if (lane >= o) x += t;
    }
    return x;
}

__global__ __launch_bounds__(1024) void k_scan() {    // 98 blocks
    __shared__ int ws[32];
    __shared__ int isLast;
    int tid = threadIdx.x, lane = tid & 31, wid = tid >> 5;
    int i = blockIdx.x * 1024 + tid;
    int v = (i < NN) ? g_cnt[i] : 0;
    int x = wscan(v, lane);
    if (lane == 31) ws[wid] = x;
    __syncthreads();
    if (wid == 0) { int w = wscan(ws[lane], lane); ws[lane] = w; }
    __syncthreads();
    int excl = x - v + (wid ? ws[wid - 1] : 0);
    if (i < NN) {
        g_off[i] = excl;                     // block-local; base added by readers
        g_inv[i] = 1.0f / (float)(v > 0 ? v : 1);
        g_cnt[i] = 0;                        // reset histogram for next replay
    }
    if (tid == 0) {
        g_btot[blockIdx.x] = ws[31];
        __threadfence();
        isLast = (atomicAdd(&g_done, 1) == 97);
    }
    __syncthreads();
    if (!isLast) return;

    __shared__ int ws2[4];
    __shared__ int tot;
    if (tid < 128) {
        int v2 = (tid < 98) ? g_btot[tid] : 0;
        int x2 = wscan(v2, lane);
        if (lane == 31) ws2[wid] = x2;
        __syncthreads();
        if (tid == 0) {
            int s = 0;
            #pragma unroll
            for (int k = 0; k < 4; ++k) { int t = ws2[k]; ws2[k] = s; s += t; }
            tot = s;
            g_done = 0;                      // reset for next graph replay
        }
        __syncthreads();
        int base = x2 - v2 + ws2[wid];
        g_bbase[tid] = base;
        if (tid == 97) g_off[NN] = tot - base;
    }
}

// ---------------- build 3: scatter (atomic-free: pos from precomputed rank) --
__global__ void k_scatter(const void* __restrict__ ei) {
    const int* w = (const int*)ei;
    bool is32 = (w[1] | w[3] | w[5] | w[7] | w[9] | w[11] | w[13] | w[15]) != 0;
    int i = (blockIdx.x * blockDim.x + threadIdx.x) * 2;
    if (i >= NE) return;
    int s0, s1;
    if (is32) {
        int2 ss = *(const int2*)((const int*)ei + i);
        s0 = ss.x; s1 = ss.y;
    } else {
        longlong2 ss = *(const longlong2*)((const long long*)ei + i);
        s0 = (int)ss.x; s1 = (int)ss.y;
    }
    int4 dr = *(const int4*)(g_dr + 2 * i);
    if (dr.x >= 0 && dr.x < NN)
        g_srcs[g_off[dr.x] + g_bbase[dr.x >> 10] + dr.y] = s0;
    if (dr.z >= 0 && dr.z < NN)
        g_srcs[g_off[dr.z] + g_bbase[dr.z >> 10] + dr.w] = s1;
}

// ---------------- mean aggregation (warp/node) + fused operand convert -------
// Unified float4 gather: layer 1 from x, layer 2 from fp32 g_h.
#define AGG_BLKS ((NN + 7) / 8)            // 12500 agg blocks
#define XBLK (NN * DD / 4 / 256)           // 12500 x-convert blocks
#define WBLK (4 * DD * DD / 256)           // 256 weight-convert blocks
__global__ __launch_bounds__(256) void k_agg(const float* __restrict__ xin,
                                             const float* __restrict__ w1l,
                                             const float* __restrict__ w1r,
                                             const float* __restrict__ w2l,
                                             const float* __restrict__ w2r,
                                             int layer) {
    if (layer == 1 && blockIdx.x >= AGG_BLKS) {
        int b2 = blockIdx.x - AGG_BLKS;
        if (b2 < XBLK) {
            int i = b2 * 256 + threadIdx.x;
            float4 v = __ldg((const float4*)xin + i);
            unsigned short h0,l0,h1,l1,h2,l2,h3,l3;
            split1(v.x,h0,l0); split1(v.y,h1,l1); split1(v.z,h2,l2); split1(v.w,h3,l3);
            ((ushort4*)g_xhi)[i] = make_ushort4(h0,h1,h2,h3);
            ((ushort4*)g_xlo)[i] = make_ushort4(l0,l1,l2,l3);
        } else {
            int i = (b2 - XBLK) * 256 + threadIdx.x;
            int m = i >> 14, j = i & (DD * DD - 1);
            const float* src = (m == 0) ? w1l : (m == 1) ? w1r : (m == 2) ? w2l : w2r;
            unsigned short* dh = (m == 0) ? g_w1lhi : (m == 1) ? g_w1rhi : (m == 2) ? g_w2lhi : g_w2rhi;
            unsigned short* dl = (m == 0) ? g_w1llo : (m == 1) ? g_w1rlo : (m == 2) ? g_w2llo : g_w2rlo;
            unsigned short h, l; split1(__ldg(&src[j]), h, l);
            dh[j] = h; dl[j] = l;
        }
        return;
    }

    const float* in = (layer == 1) ? xin : g_h;
    int node = blockIdx.x * 8 + (threadIdx.x >> 5);
    if (node >= NN) return;
    int lane = threadIdx.x & 31;
    int s = g_off[node] + g_bbase[node >> 10];
    int e = g_off[node + 1] + g_bbase[(node + 1) >> 10];
    float4 acc = make_float4(0.f, 0.f, 0.f, 0.f);
    int j = s;
    for (; j + 3 < e; j += 4) {
        int s0 = g_srcs[j], s1 = g_srcs[j+1], s2 = g_srcs[j+2], s3 = g_srcs[j+3];
        float4 a = __ldg((const float4*)(in + (size_t)s0 * DD + lane * 4));
        float4 b = __ldg((const float4*)(in + (size_t)s1 * DD + lane * 4));
        float4 c = __ldg((const float4*)(in + (size_t)s2 * DD + lane * 4));
        float4 d = __ldg((const float4*)(in + (size_t)s3 * DD + lane * 4));
        acc.x += a.x + b.x + c.x + d.x;
        acc.y += a.y + b.y + c.y + d.y;
        acc.z += a.z + b.z + c.z + d.z;
        acc.w += a.w + b.w + c.w + d.w;
    }
    for (; j < e; ++j) {
        int s0 = g_srcs[j];
        float4 a = __ldg((const float4*)(in + (size_t)s0 * DD + lane * 4));
        acc.x += a.x; acc.y += a.y; acc.z += a.z; acc.w += a.w;
    }
    float inv = g_inv[node];
    acc.x *= inv; acc.y *= inv; acc.z *= inv; acc.w *= inv;
    unsigned short h0,l0,h1,l1,h2,l2,h3,l3;
    split1(acc.x,h0,l0); split1(acc.y,h1,l1); split1(acc.z,h2,l2); split1(acc.w,h3,l3);
    size_t o4 = (size_t)node * (DD/4) + lane;
    ((ushort4*)g_mhi)[o4] = make_ushort4(h0,h1,h2,h3);
    ((ushort4*)g_mlo)[o4] = make_ushort4(l0,l1,l2,l3);
}

// ---------------- tensor-core concat-GEMM: 32-k chunks, 1 sync/iter ----------
#define PA 40
#define PB 264
#define A_US(buf,hl,r,k) (((buf)*2+(hl))*5120 + (r)*PA + (k))
#define B_US(hl,n,k)     (20480 + (hl)*16896 + (n)*PB + (k))
#define SMEM_GEMM ((20480 + 2*16896) * 2)                        // 108544 B

__device__ __forceinline__ uint32_t smem_u32(const void* p) {
    uint32_t a;
    asm("{ .reg .u64 t; cvta.to.shared.u64 t, %1; cvt.u32.u64 %0, t; }" : "=r"(a) : "l"(p));
    return a;
}
__device__ __forceinline__ void cpa16(uint32_t dst, const void* src) {
    asm volatile("cp.async.cg.shared.global [%0], [%1], 16;" :: "r"(dst), "l"(src));
}
__device__ __forceinline__ void mma16816(float* c, const uint32_t* a, uint32_t b0, uint32_t b1) {
    asm volatile("mma.sync.aligned.m16n8k16.row.col.f32.bf16.bf16.f32 "
        "{%0,%1,%2,%3},{%4,%5,%6,%7},{%8,%9},{%0,%1,%2,%3};"
        : "+f"(c[0]), "+f"(c[1]), "+f"(c[2]), "+f"(c[3])
        : "r"(a[0]), "r"(a[1]), "r"(a[2]), "r"(a[3]), "r"(b0), "r"(b1));
}

__global__ __launch_bounds__(256) void k_gemm_mma(
    const float* __restrict__ bias, float* __restrict__ out2, int layer)
{
    extern __shared__ unsigned short smu[];
    uint32_t sb = smem_u32(smu);
    int tid = threadIdx.x, lane = tid & 31, warp = tid >> 5;
    int wm = warp & 3, wn = warp >> 2;
    int g = lane >> 2, t = lane & 3;
    int m0 = blockIdx.x * 128;
    int n0 = blockIdx.y * 64;

    #pragma unroll
    for (int half = 0; half < 2; ++half) {
        const unsigned short *wh, *wl;
        if (layer == 1) { wh = half ? g_w1rhi : g_w1lhi; wl = half ? g_w1rlo : g_w1llo; }
        else            { wh = half ? g_w2rhi : g_w2lhi; wl = half ? g_w2rlo : g_w2llo; }
        #pragma unroll
        for (int ii = 0; ii < 4; ++ii) {
            int c = tid + ii * 256;
            int row = c >> 4, kq = (c & 15) * 8;
            int gb = n0 + row;
            uint4 vH = *(const uint4*)(wh + (size_t)gb * DD + kq);
            uint4 vL = *(const uint4*)(wl + (size_t)gb * DD + kq);
            *(uint4*)&smu[B_US(0, row, half * 128 + kq)] = vH;
            *(uint4*)&smu[B_US(1, row, half * 128 + kq)] = vL;
        }
    }

    int arow = tid >> 1, acb = (tid & 1) * 16;
    auto issueA = [&](int idx, int buf) {
        int stage = idx >> 2, kb = (idx & 3) * 32;
        const unsigned short *ah, *al;
        if (stage == 0) { ah = g_mhi; al = g_mlo; }
        else if (layer == 1) { ah = g_xhi; al = g_xlo; }
        else { ah = g_hhi; al = g_hlo; }
        int ga = m0 + arow;
        if (ga < NN) {
            const unsigned short* sH = ah + (size_t)ga * DD + kb + acb;
            const unsigned short* sL = al + (size_t)ga * DD + kb + acb;
            cpa16(sb + 2 * A_US(buf, 0, arow, acb),     sH);
            cpa16(sb + 2 * A_US(buf, 0, arow, acb + 8), sH + 8);
            cpa16(sb + 2 * A_US(buf, 1, arow, acb),     sL);
            cpa16(sb + 2 * A_US(buf, 1, arow, acb + 8), sL + 8);
        }
    };

    float c[2][4][4];
    #pragma unroll
    for (int mt = 0; mt < 2; ++mt)
        #pragma unroll
        for (int nt = 0; nt < 4; ++nt)
            #pragma unroll
            for (int q = 0; q < 4; ++q) c[mt][nt][q] = 0.f;

    issueA(0, 0);
    asm volatile("cp.async.commit_group;");

    #pragma unroll 1
    for (int idx = 0; idx < 8; ++idx) {
        int buf = idx & 1;
        asm volatile("cp.async.wait_group 0;");
        __syncthreads();
        if (idx < 7) {
            issueA(idx + 1, buf ^ 1);
            asm volatile("cp.async.commit_group;");
        }

        int kg0 = (idx >> 2) * 128 + (idx & 3) * 32;
        #pragma unroll
        for (int kc = 0; kc < 32; kc += 16) {
            uint32_t af[2][2][4];
            #pragma unroll
            for (int mt = 0; mt < 2; ++mt) {
                int r = wm * 32 + mt * 16;
                #pragma unroll
                for (int hl = 0; hl < 2; ++hl) {
                    af[mt][hl][0] = *(const uint32_t*)&smu[A_US(buf, hl, r + g,     kc + 2*t)];
                    af[mt][hl][1] = *(const uint32_t*)&smu[A_US(buf, hl, r + g + 8, kc + 2*t)];
                    af[mt][hl][2] = *(const uint32_t*)&smu[A_US(buf, hl, r + g,     kc + 2*t + 8)];
                    af[mt][hl][3] = *(const uint32_t*)&smu[A_US(buf, hl, r + g + 8, kc + 2*t + 8)];
                }
            }
            int kB = kg0 + kc;
            #pragma unroll
            for (int nt = 0; nt < 4; ++nt) {
                int n = wn * 32 + nt * 8;
                uint32_t bh0 = *(const uint32_t*)&smu[B_US(0, n + g, kB + 2*t)];
                uint32_t bh1 = *(const uint32_t*)&smu[B_US(0, n + g, kB + 2*t + 8)];
                uint32_t bl0 = *(const uint32_t*)&smu[B_US(1, n + g, kB + 2*t)];
                uint32_t bl1 = *(const uint32_t*)&smu[B_US(1, n + g, kB + 2*t + 8)];
                #pragma unroll
                for (int mt = 0; mt < 2; ++mt) {
                    mma16816(c[mt][nt], af[mt][0], bh0, bh1);   // hh
                    mma16816(c[mt][nt], af[mt][0], bl0, bl1);   // hl
                    mma16816(c[mt][nt], af[mt][1], bh0, bh1);   // lh
                }
            }
        }
    }

    #pragma unroll
    for (int mt = 0; mt < 2; ++mt) {
        #pragma unroll
        for (int half = 0; half < 2; ++half) {
            int node = m0 + wm*32 + mt*16 + g + half*8;
            if (node >= NN) continue;
            #pragma unroll
            for (int nt = 0; nt < 4; ++nt) {
                int col = n0 + wn*32 + nt*8 + 2*t;
                float v0 = c[mt][nt][half*2 + 0] + __ldg(&bias[col]);
                float v1 = c[mt][nt][half*2 + 1] + __ldg(&bias[col + 1]);
                if (layer == 1) {
                    v0 = fmaxf(v0, 0.f); v1 = fmaxf(v1, 0.f);
                    *(float2*)(g_h + (size_t)node*DD + col) = make_float2(v0, v1);
                    unsigned short h0,l0,h1,l1;
                    split1(v0,h0,l0); split1(v1,h1,l1);
                    *(ushort2*)(g_hhi + (size_t)node*DD + col) = make_ushort2(h0,h1);
                    *(ushort2*)(g_hlo + (size_t)node*DD + col) = make_ushort2(l0,l1);
                } else {
                    *(float2*)(out2 + (size_t)node*DD + col) = make_float2(v0, v1);
                }
            }
        }
    }
}

// ---------------- launch ----------------------------------------------------
extern "C" void kernel_launch(void* const* d_in, const int* in_sizes, int n_in,
                              void* d_out, int out_size) {
    const float* x   = (const float*)d_in[0];
    const void*  ei  = d_in[1];
    const float* W1l = (const float*)d_in[2];
    const float* b1l = (const float*)d_in[3];
    const float* W1r = (const float*)d_in[4];
    const float* W2l = (const float*)d_in[5];
    const float* b2l = (const float*)d_in[6];
    const float* W2r = (const float*)d_in[7];
    float* out = (float*)d_out;

    cudaFuncSetAttribute(k_gemm_mma, cudaFuncAttributeMaxDynamicSharedMemorySize, SMEM_GEMM);

    int scanGrid = (NN + 1023) / 1024;     // 98
    int edgeGrid = (NE / 2 + 255) / 256;   // 2 edges per thread
    dim3 gemmGrid((NN + 127) / 128, 2);

    k_hist<<<edgeGrid, 256>>>(ei);
    k_scan<<<scanGrid, 1024>>>();
    k_scatter<<<edgeGrid, 256>>>(ei);

    // layer 1: agg + fused x/w bf16-split convert (extra blocks), then GEMM
    k_agg<<<AGG_BLKS + XBLK + WBLK, 256>>>(x, W1l, W1r, W2l, W2r, 1);  // profiled
    k_gemm_mma<<<gemmGrid, 256, SMEM_GEMM>>>(b1l, (float*)0, 1);
    // layer 2: out = [mean(h)||h] @ [W2l||W2r]^T + b2
    k_agg<<<AGG_BLKS, 256>>>(x, W1l, W1r, W2l, W2r, 2);
    k_gemm_mma<<<gemmGrid, 256, SMEM_GEMM>>>(b2l, out, 2);
}

// round 16
// speedup vs baseline: 1.0547x; 1.0547x over previous
#include <cuda_runtime.h>
#include <cuda_bf16.h>
#include <cstdint>

#define NN 100000
#define NE 1600000
#define DD 128

// ---------------- scratch (device globals; referenced ONLY in device code) --
__device__ int   g_off[NN + 1];
__device__ int   g_cnt[NN];         // histogram; k_scan zeroes it for replays
__device__ float g_inv[NN];
__device__ int   g_btot[128];
__device__ int   g_bbase[128];
__device__ int   g_done;            // scan last-block counter (self-resetting)
__device__ __align__(16) int g_srcs[NE];
__device__ __align__(16) int g_dr[2 * NE];   // (dst, rank) pairs
__device__ __align__(16) float g_h[NN * DD]; // fp32 hidden acts (for agg2 gather)
__device__ __align__(16) unsigned short g_xhi[NN * DD], g_xlo[NN * DD];
__device__ __align__(16) unsigned short g_mhi[NN * DD], g_mlo[NN * DD];
__device__ __align__(16) unsigned short g_hhi[NN * DD], g_hlo[NN * DD];
__device__ __align__(16) unsigned short g_w1lhi[DD*DD], g_w1llo[DD*DD];
__device__ __align__(16) unsigned short g_w1rhi[DD*DD], g_w1rlo[DD*DD];
__device__ __align__(16) unsigned short g_w2lhi[DD*DD], g_w2llo[DD*DD];
__device__ __align__(16) unsigned short g_w2rhi[DD*DD], g_w2rlo[DD*DD];

__device__ __forceinline__ void split1(float v, unsigned short& hi, unsigned short& lo) {
    __nv_bfloat16 h = __float2bfloat16(v);
    __nv_bfloat16 l = __float2bfloat16(v - __bfloat162float(h));
    hi = *(unsigned short*)&h; lo = *(unsigned short*)&l;
}

// ---------------- build 1: dst convert + histogram + rank (2 edges/thread) --
__global__ void k_hist(const void* __restrict__ ei) {
    const int* w = (const int*)ei;
    bool is32 = (w[1] | w[3] | w[5] | w[7] | w[9] | w[11] | w[13] | w[15]) != 0;
    int i = (blockIdx.x * blockDim.x + threadIdx.x) * 2;
    if (i >= NE) return;
    int d0, d1;
    if (is32) {
        int2 dd = *(const int2*)((const int*)ei + NE + i);
        d0 = dd.x; d1 = dd.y;
    } else {
        longlong2 dd = *(const longlong2*)((const long long*)ei + NE + i);
        d0 = (int)dd.x; d1 = (int)dd.y;
    }
    int r0 = 0, r1 = 0;
    if (d0 >= 0 && d0 < NN) r0 = atomicAdd(&g_cnt[d0], 1);
    if (d1 >= 0 && d1 < NN) r1 = atomicAdd(&g_cnt[d1], 1);
    *(int4*)(g_dr + 2 * i) = make_int4(d0, r0, d1, r1);
}

// ---------------- build 2: scan (fused level-2, zeroes g_cnt for replays) ---
__device__ __forceinline__ int wscan(int x, int lane) {
    #pragma unroll
    for (int o = 1; o < 32; o <<= 1) {
        int t = __shfl_up_sync(0xffffffffu, x, o);
        if (lane >= o) x += t;
    }
    return x;
}

__global__ __launch_bounds__(1024) void k_scan() {    // 98 blocks
    __shared__ int ws[32];
    __shared__ int isLast;
    int tid = threadIdx.x, lane = tid & 31, wid = tid >> 5;
    int i = blockIdx.x * 1024 + tid;
    int v = (i < NN) ? g_cnt[i] : 0;
    int x = wscan(v, lane);
    if (lane == 31) ws[wid] = x;
    __syncthreads();
    if (wid == 0) { int w = wscan(ws[lane], lane); ws[lane] = w; }
    __syncthreads();
    int excl = x - v + (wid ? ws[wid - 1] : 0);
    if (i < NN) {
        g_off[i] = excl;                     // block-local; base added by readers
        g_inv[i] = 1.0f / (float)(v > 0 ? v : 1);
        g_cnt[i] = 0;                        // reset histogram for next replay
    }
    if (tid == 0) {
        g_btot[blockIdx.x] = ws[31];
        __threadfence();
        isLast = (atomicAdd(&g_done, 1) == 97);
    }
    __syncthreads();
    if (!isLast) return;

    __shared__ int ws2[4];
    __shared__ int tot;
    if (tid < 128) {
        int v2 = (tid < 98) ? g_btot[tid] : 0;
        int x2 = wscan(v2, lane);
        if (lane == 31) ws2[wid] = x2;
        __syncthreads();
        if (tid == 0) {
            int s = 0;
            #pragma unroll
            for (int k = 0; k < 4; ++k) { int t = ws2[k]; ws2[k] = s; s += t; }
            tot = s;
            g_done = 0;                      // reset for next graph replay
        }
        __syncthreads();
        int base = x2 - v2 + ws2[wid];
        g_bbase[tid] = base;
        if (tid == 97) g_off[NN] = tot - base;
    }
}

// ---------------- build 3: scatter (atomic-free: pos from precomputed rank) --
__global__ void k_scatter(const void* __restrict__ ei) {
    const int* w = (const int*)ei;
    bool is32 = (w[1] | w[3] | w[5] | w[7] | w[9] | w[11] | w[13] | w[15]) != 0;
    int i = (blockIdx.x * blockDim.x + threadIdx.x) * 2;
    if (i >= NE) return;
    int s0, s1;
    if (is32) {
        int2 ss = *(const int2*)((const int*)ei + i);
        s0 = ss.x; s1 = ss.y;
    } else {
        longlong2 ss = *(const longlong2*)((const long long*)ei + i);
        s0 = (int)ss.x; s1 = (int)ss.y;
    }
    int4 dr = *(const int4*)(g_dr + 2 * i);
    if (dr.x >= 0 && dr.x < NN)
        g_srcs[g_off[dr.x] + g_bbase[dr.x >> 10] + dr.y] = s0;
    if (dr.z >= 0 && dr.z < NN)
        g_srcs[g_off[dr.z] + g_bbase[dr.z >> 10] + dr.w] = s1;
}

// ---------------- mean aggregation (warp/node) + fused operand convert -------
// Unified float4 gather: layer 1 from x, layer 2 from fp32 g_h.
// __launch_bounds__(256, 8): pin regs to 32 so 8 CTAs/SM stay resident
// (round-15 showed ptxas drifting to 40 regs -> occ 59% -> +10us on agg).
#define AGG_BLKS ((NN + 7) / 8)            // 12500 agg blocks
#define XBLK (NN * DD / 4 / 256)           // 12500 x-convert blocks
#define WBLK (4 * DD * DD / 256)           // 256 weight-convert blocks
__global__ __launch_bounds__(256, 8) void k_agg(const float* __restrict__ xin,
                                                const float* __restrict__ w1l,
                                                const float* __restrict__ w1r,
                                                const float* __restrict__ w2l,
                                                const float* __restrict__ w2r,
                                                int layer) {
    if (layer == 1 && blockIdx.x >= AGG_BLKS) {
        int b2 = blockIdx.x - AGG_BLKS;
        if (b2 < XBLK) {
            int i = b2 * 256 + threadIdx.x;
            float4 v = __ldg((const float4*)xin + i);
            unsigned short h0,l0,h1,l1,h2,l2,h3,l3;
            split1(v.x,h0,l0); split1(v.y,h1,l1); split1(v.z,h2,l2); split1(v.w,h3,l3);
            ((ushort4*)g_xhi)[i] = make_ushort4(h0,h1,h2,h3);
            ((ushort4*)g_xlo)[i] = make_ushort4(l0,l1,l2,l3);
        } else {
            int i = (b2 - XBLK) * 256 + threadIdx.x;
            int m = i >> 14, j = i & (DD * DD - 1);
            const float* src = (m == 0) ? w1l : (m == 1) ? w1r : (m == 2) ? w2l : w2r;
            unsigned short* dh = (m == 0) ? g_w1lhi : (m == 1) ? g_w1rhi : (m == 2) ? g_w2lhi : g_w2rhi;
            unsigned short* dl = (m == 0) ? g_w1llo : (m == 1) ? g_w1rlo : (m == 2) ? g_w2llo : g_w2rlo;
            unsigned short h, l; split1(__ldg(&src[j]), h, l);
            dh[j] = h; dl[j] = l;
        }
        return;
    }

    const float* in = (layer == 1) ? xin : g_h;
    int node = blockIdx.x * 8 + (threadIdx.x >> 5);
    if (node >= NN) return;
    int lane = threadIdx.x & 31;
    int s = g_off[node] + g_bbase[node >> 10];
    int e = g_off[node + 1] + g_bbase[(node + 1) >> 10];
    float4 acc = make_float4(0.f, 0.f, 0.f, 0.f);
    int j = s;
    for (; j + 3 < e; j += 4) {
        int s0 = g_srcs[j], s1 = g_srcs[j+1], s2 = g_srcs[j+2], s3 = g_srcs[j+3];
        float4 a = __ldg((const float4*)(in + (size_t)s0 * DD + lane * 4));
        float4 b = __ldg((const float4*)(in + (size_t)s1 * DD + lane * 4));
        float4 c = __ldg((const float4*)(in + (size_t)s2 * DD + lane * 4));
        float4 d = __ldg((const float4*)(in + (size_t)s3 * DD + lane * 4));
        acc.x += a.x + b.x + c.x + d.x;
        acc.y += a.y + b.y + c.y + d.y;
        acc.z += a.z + b.z + c.z + d.z;
        acc.w += a.w + b.w + c.w + d.w;
    }
    for (; j < e; ++j) {
        int s0 = g_srcs[j];
        float4 a = __ldg((const float4*)(in + (size_t)s0 * DD + lane * 4));
        acc.x += a.x; acc.y += a.y; acc.z += a.z; acc.w += a.w;
    }
    float inv = g_inv[node];
    acc.x *= inv; acc.y *= inv; acc.z *= inv; acc.w *= inv;
    unsigned short h0,l0,h1,l1,h2,l2,h3,l3;
    split1(acc.x,h0,l0); split1(acc.y,h1,l1); split1(acc.z,h2,l2); split1(acc.w,h3,l3);
    size_t o4 = (size_t)node * (DD/4) + lane;
    ((ushort4*)g_mhi)[o4] = make_ushort4(h0,h1,h2,h3);
    ((ushort4*)g_mlo)[o4] = make_ushort4(l0,l1,l2,l3);
}

// ---------------- tensor-core concat-GEMM: 32-k chunks, 1 sync/iter ----------
#define PA 40
#define PB 264
#define A_US(buf,hl,r,k) (((buf)*2+(hl))*5120 + (r)*PA + (k))
#define B_US(hl,n,k)     (20480 + (hl)*16896 + (n)*PB + (k))
#define SMEM_GEMM ((20480 + 2*16896) * 2)                        // 108544 B

__device__ __forceinline__ uint32_t smem_u32(const void* p) {
    uint32_t a;
    asm("{ .reg .u64 t; cvta.to.shared.u64 t, %1; cvt.u32.u64 %0, t; }" : "=r"(a) : "l"(p));
    return a;
}
__device__ __forceinline__ void cpa16(uint32_t dst, const void* src) {
    asm volatile("cp.async.cg.shared.global [%0], [%1], 16;" :: "r"(dst), "l"(src));
}
__device__ __forceinline__ void mma16816(float* c, const uint32_t* a, uint32_t b0, uint32_t b1) {
    asm volatile("mma.sync.aligned.m16n8k16.row.col.f32.bf16.bf16.f32 "
        "{%0,%1,%2,%3},{%4,%5,%6,%7},{%8,%9},{%0,%1,%2,%3};"
        : "+f"(c[0]), "+f"(c[1]), "+f"(c[2]), "+f"(c[3])
        : "r"(a[0]), "r"(a[1]), "r"(a[2]), "r"(a[3]), "r"(b0), "r"(b1));
}

__global__ __launch_bounds__(256) void k_gemm_mma(
    const float* __restrict__ bias, float* __restrict__ out2, int layer)
{
    extern __shared__ unsigned short smu[];
    uint32_t sb = smem_u32(smu);
    int tid = threadIdx.x, lane = tid & 31, warp = tid >> 5;
    int wm = warp & 3, wn = warp >> 2;
    int g = lane >> 2, t = lane & 3;
    int m0 = blockIdx.x * 128;
    int n0 = blockIdx.y * 64;

    #pragma unroll
    for (int half = 0; half < 2; ++half) {
        const unsigned short *wh, *wl;
        if (layer == 1) { wh = half ? g_w1rhi : g_w1lhi; wl = half ? g_w1rlo : g_w1llo; }
        else            { wh = half ? g_w2rhi : g_w2lhi; wl = half ? g_w2rlo : g_w2llo; }
        #pragma unroll
        for (int ii = 0; ii < 4; ++ii) {
            int c = tid + ii * 256;
            int row = c >> 4, kq = (c & 15) * 8;
            int gb = n0 + row;
            uint4 vH = *(const uint4*)(wh + (size_t)gb * DD + kq);
            uint4 vL = *(const uint4*)(wl + (size_t)gb * DD + kq);
            *(uint4*)&smu[B_US(0, row, half * 128 + kq)] = vH;
            *(uint4*)&smu[B_US(1, row, half * 128 + kq)] = vL;
        }
    }

    int arow = tid >> 1, acb = (tid & 1) * 16;
    auto issueA = [&](int idx, int buf) {
        int stage = idx >> 2, kb = (idx & 3) * 32;
        const unsigned short *ah, *al;
        if (stage == 0) { ah = g_mhi; al = g_mlo; }
        else if (layer == 1) { ah = g_xhi; al = g_xlo; }
        else { ah = g_hhi; al = g_hlo; }
        int ga = m0 + arow;
        if (ga < NN) {
            const unsigned short* sH = ah + (size_t)ga * DD + kb + acb;
            const unsigned short* sL = al + (size_t)ga * DD + kb + acb;
            cpa16(sb + 2 * A_US(buf, 0, arow, acb),     sH);
            cpa16(sb + 2 * A_US(buf, 0, arow, acb + 8), sH + 8);
            cpa16(sb + 2 * A_US(buf, 1, arow, acb),     sL);
            cpa16(sb + 2 * A_US(buf, 1, arow, acb + 8), sL + 8);
        }
    };

    float c[2][4][4];
    #pragma unroll
    for (int mt = 0; mt < 2; ++mt)
        #pragma unroll
        for (int nt = 0; nt < 4; ++nt)
            #pragma unroll
            for (int q = 0; q < 4; ++q) c[mt][nt][q] = 0.f;

    issueA(0, 0);
    asm volatile("cp.async.commit_group;");

    #pragma unroll 1
    for (int idx = 0; idx < 8; ++idx) {
        int buf = idx & 1;
        asm volatile("cp.async.wait_group 0;");
        __syncthreads();
        if (idx < 7) {
            issueA(idx + 1, buf ^ 1);
            asm volatile("cp.async.commit_group;");
        }

        int kg0 = (idx >> 2) * 128 + (idx & 3) * 32;
        #pragma unroll
        for (int kc = 0; kc < 32; kc += 16) {
            uint32_t af[2][2][4];
            #pragma unroll
            for (int mt = 0; mt < 2; ++mt) {
                int r = wm * 32 + mt * 16;
                #pragma unroll
                for (int hl = 0; hl < 2; ++hl) {
                    af[mt][hl][0] = *(const uint32_t*)&smu[A_US(buf, hl, r + g,     kc + 2*t)];
                    af[mt][hl][1] = *(const uint32_t*)&smu[A_US(buf, hl, r + g + 8, kc + 2*t)];
                    af[mt][hl][2] = *(const uint32_t*)&smu[A_US(buf, hl, r + g,     kc + 2*t + 8)];
                    af[mt][hl][3] = *(const uint32_t*)&smu[A_US(buf, hl, r + g + 8, kc + 2*t + 8)];
                }
            }
            int kB = kg0 + kc;
            #pragma unroll
            for (int nt = 0; nt < 4; ++nt) {
                int n = wn * 32 + nt * 8;
                uint32_t bh0 = *(const uint32_t*)&smu[B_US(0, n + g, kB + 2*t)];
                uint32_t bh1 = *(const uint32_t*)&smu[B_US(0, n + g, kB + 2*t + 8)];
                uint32_t bl0 = *(const uint32_t*)&smu[B_US(1, n + g, kB + 2*t)];
                uint32_t bl1 = *(const uint32_t*)&smu[B_US(1, n + g, kB + 2*t + 8)];
                #pragma unroll
                for (int mt = 0; mt < 2; ++mt) {
                    mma16816(c[mt][nt], af[mt][0], bh0, bh1);   // hh
                    mma16816(c[mt][nt], af[mt][0], bl0, bl1);   // hl
                    mma16816(c[mt][nt], af[mt][1], bh0, bh1);   // lh
                }
            }
        }
    }

    #pragma unroll
    for (int mt = 0; mt < 2; ++mt) {
        #pragma unroll
        for (int half = 0; half < 2; ++half) {
            int node = m0 + wm*32 + mt*16 + g + half*8;
            if (node >= NN) continue;
            #pragma unroll
            for (int nt = 0; nt < 4; ++nt) {
                int col = n0 + wn*32 + nt*8 + 2*t;
                float v0 = c[mt][nt][half*2 + 0] + __ldg(&bias[col]);
                float v1 = c[mt][nt][half*2 + 1] + __ldg(&bias[col + 1]);
                if (layer == 1) {
                    v0 = fmaxf(v0, 0.f); v1 = fmaxf(v1, 0.f);
                    *(float2*)(g_h + (size_t)node*DD + col) = make_float2(v0, v1);
                    unsigned short h0,l0,h1,l1;
                    split1(v0,h0,l0); split1(v1,h1,l1);
                    *(ushort2*)(g_hhi + (size_t)node*DD + col) = make_ushort2(h0,h1);
                    *(ushort2*)(g_hlo + (size_t)node*DD + col) = make_ushort2(l0,l1);
                } else {
                    *(float2*)(out2 + (size_t)node*DD + col) = make_float2(v0, v1);
                }
            }
        }
    }
}

// ---------------- launch ----------------------------------------------------
extern "C" void kernel_launch(void* const* d_in, const int* in_sizes, int n_in,
                              void* d_out, int out_size) {
    const float* x   = (const float*)d_in[0];
    const void*  ei  = d_in[1];
    const float* W1l = (const float*)d_in[2];
    const float* b1l = (const float*)d_in[3];
    const float* W1r = (const float*)d_in[4];
    const float* W2l = (const float*)d_in[5];
    const float* b2l = (const float*)d_in[6];
    const float* W2r = (const float*)d_in[7];
    float* out = (float*)d_out;

    cudaFuncSetAttribute(k_gemm_mma, cudaFuncAttributeMaxDynamicSharedMemorySize, SMEM_GEMM);

    int scanGrid = (NN + 1023) / 1024;     // 98
    int edgeGrid = (NE / 2 + 255) / 256;   // 2 edges per thread
    dim3 gemmGrid((NN + 127) / 128, 2);

    k_hist<<<edgeGrid, 256>>>(ei);
    k_scan<<<scanGrid, 1024>>>();
    k_scatter<<<edgeGrid, 256>>>(ei);

    // layer 1: agg + fused x/w bf16-split convert (extra blocks), then GEMM
    k_agg<<<AGG_BLKS + XBLK + WBLK, 256>>>(x, W1l, W1r, W2l, W2r, 1);  // profiled
    k_gemm_mma<<<gemmGrid, 256, SMEM_GEMM>>>(b1l, (float*)0, 1);
    // layer 2: out = [mean(h)||h] @ [W2l||W2r]^T + b2
    k_agg<<<AGG_BLKS, 256>>>(x, W1l, W1r, W2l, W2r, 2);
    k_gemm_mma<<<gemmGrid, 256, SMEM_GEMM>>>(b2l, out, 2);
}